// round 2
// baseline (speedup 1.0000x reference)
#include <cuda_runtime.h>
#include <cuda_bf16.h>
#include <cstdint>
#include <cstddef>

// ============================================================================
// Problem sizes
// ============================================================================
#define BATCH 4
#define SEQ   8192
#define DIM   1024
#define MTOT  (BATCH*SEQ)      // 32768 rows
#define NTOT  (2*DIM)          // 2048 combined output cols (gate | cand)
#define CHUNK_T 128            // scan chunk length
#define NCH   (SEQ/CHUNK_T)    // 64 chunks per (b,d) channel

// ============================================================================
// Scratch (static device arrays — no allocation allowed)
// ============================================================================
__device__ __nv_bfloat16 g_xhi[(size_t)MTOT*DIM];   // 64 MB
__device__ __nv_bfloat16 g_xlo[(size_t)MTOT*DIM];   // 64 MB
__device__ __nv_bfloat16 g_whi[(size_t)NTOT*DIM];   // 4 MB  (Wg rows 0..1023, Wc rows 1024..2047)
__device__ __nv_bfloat16 g_wlo[(size_t)NTOT*DIM];   // 4 MB
__device__ float g_gate[(size_t)MTOT*DIM];          // 128 MB
__device__ float g_cand[(size_t)MTOT*DIM];          // 128 MB
__device__ float g_Ast[(size_t)BATCH*NCH*DIM];      // 1 MB
__device__ float g_Hst[(size_t)BATCH*NCH*DIM];      // 1 MB
__device__ float g_Pst[(size_t)BATCH*NCH*DIM];      // 1 MB

// ============================================================================
// Helpers (non-'a' PTX only: cp.async, ldmatrix, mma.sync)
// ============================================================================
__device__ __forceinline__ uint32_t smem_u32(const void* p){
    uint32_t a;
    asm("{ .reg .u64 t; cvta.to.shared.u64 t, %1; cvt.u32.u64 %0, t; }" : "=r"(a) : "l"(p));
    return a;
}
__device__ __forceinline__ void cp16(uint32_t smem_addr, const void* gptr){
    asm volatile("cp.async.cg.shared.global [%0], [%1], 16;"
                 :: "r"(smem_addr), "l"(__cvta_generic_to_global(gptr)) : "memory");
}
#define CP_COMMIT()  asm volatile("cp.async.commit_group;" ::: "memory")
#define CP_WAIT(n)   asm volatile("cp.async.wait_group %0;" :: "n"(n) : "memory")

__device__ __forceinline__ void ldsm4(uint32_t* r, uint32_t addr){
    asm volatile("ldmatrix.sync.aligned.m8n8.x4.shared.b16 {%0,%1,%2,%3}, [%4];"
                 : "=r"(r[0]),"=r"(r[1]),"=r"(r[2]),"=r"(r[3]) : "r"(addr));
}
__device__ __forceinline__ void mma16816(float* d, const uint32_t* a, const uint32_t* b){
    asm volatile("mma.sync.aligned.m16n8k16.row.col.f32.bf16.bf16.f32 "
                 "{%0,%1,%2,%3}, {%4,%5,%6,%7}, {%8,%9}, {%0,%1,%2,%3};"
                 : "+f"(d[0]),"+f"(d[1]),"+f"(d[2]),"+f"(d[3])
                 : "r"(a[0]),"r"(a[1]),"r"(a[2]),"r"(a[3]), "r"(b[0]),"r"(b[1]));
}

__device__ __forceinline__ float sigmoid_f(float v){
    return 1.0f / (1.0f + __expf(-v));
}
__device__ __forceinline__ float tanh_f(float v){
    float a = fabsf(v);
    float e = __expf(-2.0f * a);
    float t = (1.0f - e) / (1.0f + e);
    return copysignf(t, v);
}

// ============================================================================
// Kernel 1: convert x (fp32) -> xhi/xlo (bf16 split)
// ============================================================================
__global__ void conv_x_kernel(const float* __restrict__ x){
    size_t i = ((size_t)blockIdx.x * blockDim.x + threadIdx.x) * 4;
    float4 v = *reinterpret_cast<const float4*>(x + i);
    __nv_bfloat16 h0 = __float2bfloat16(v.x);
    __nv_bfloat16 h1 = __float2bfloat16(v.y);
    __nv_bfloat16 h2 = __float2bfloat16(v.z);
    __nv_bfloat16 h3 = __float2bfloat16(v.w);
    __nv_bfloat16 l0 = __float2bfloat16(v.x - __bfloat162float(h0));
    __nv_bfloat16 l1 = __float2bfloat16(v.y - __bfloat162float(h1));
    __nv_bfloat16 l2 = __float2bfloat16(v.z - __bfloat162float(h2));
    __nv_bfloat16 l3 = __float2bfloat16(v.w - __bfloat162float(h3));
    __nv_bfloat162* ph = reinterpret_cast<__nv_bfloat162*>(g_xhi + i);
    __nv_bfloat162* pl = reinterpret_cast<__nv_bfloat162*>(g_xlo + i);
    ph[0] = __nv_bfloat162(h0, h1); ph[1] = __nv_bfloat162(h2, h3);
    pl[0] = __nv_bfloat162(l0, l1); pl[1] = __nv_bfloat162(l2, l3);
}

// ============================================================================
// Kernel 2: convert [Wg;Wc] -> whi/wlo (bf16 split), concatenated rows
// ============================================================================
__global__ void conv_w_kernel(const float* __restrict__ Wg, const float* __restrict__ Wc){
    size_t i = ((size_t)blockIdx.x * blockDim.x + threadIdx.x) * 4;
    const size_t HALF = (size_t)DIM * DIM;
    float4 v = (i < HALF) ? *reinterpret_cast<const float4*>(Wg + i)
                          : *reinterpret_cast<const float4*>(Wc + (i - HALF));
    __nv_bfloat16 h0 = __float2bfloat16(v.x);
    __nv_bfloat16 h1 = __float2bfloat16(v.y);
    __nv_bfloat16 h2 = __float2bfloat16(v.z);
    __nv_bfloat16 h3 = __float2bfloat16(v.w);
    __nv_bfloat16 l0 = __float2bfloat16(v.x - __bfloat162float(h0));
    __nv_bfloat16 l1 = __float2bfloat16(v.y - __bfloat162float(h1));
    __nv_bfloat16 l2 = __float2bfloat16(v.z - __bfloat162float(h2));
    __nv_bfloat16 l3 = __float2bfloat16(v.w - __bfloat162float(h3));
    __nv_bfloat162* ph = reinterpret_cast<__nv_bfloat162*>(g_whi + i);
    __nv_bfloat162* pl = reinterpret_cast<__nv_bfloat162*>(g_wlo + i);
    ph[0] = __nv_bfloat162(h0, h1); ph[1] = __nv_bfloat162(h2, h3);
    pl[0] = __nv_bfloat162(l0, l1); pl[1] = __nv_bfloat162(l2, l3);
}

// ============================================================================
// Kernel 3: fused dual GEMM (mma.sync bf16, 3-term hi/lo split)
//   D[m, 0:2048] = x @ [Wg;Wc]^T ; cols < 1024 -> sigmoid -> g_gate
//                                  cols >= 1024 -> tanh   -> g_cand
// ============================================================================
#define BM 128
#define BN 128
#define BK 32
#define NSTAGE 4
#define KITER (DIM/BK)           // 32
#define ROWB 64                  // bytes per smem row (32 bf16)
#define TILE_BYTES (128*ROWB)    // 8192 per matrix per stage
#define STAGE_BYTES (4*TILE_BYTES)  // Ahi|Alo|Bhi|Blo = 32768
#define GEMM_SMEM (NSTAGE*STAGE_BYTES + 128)

__global__ void __launch_bounds__(256, 1)
gemm_kernel(const float* __restrict__ bg, const float* __restrict__ bc){
    extern __shared__ char smem[];
    const uint32_t tb = (smem_u32(smem) + 127u) & ~127u;   // 128B-aligned tile base
    const int tid = threadIdx.x;
    const int wid = tid >> 5;
    const int lid = tid & 31;
    const int wm = wid >> 2;           // 0..1  (64-row slabs)
    const int wn = wid & 3;            // 0..3  (32-col slabs)
    const int n0 = blockIdx.x * BN;
    const int m0 = blockIdx.y * BM;

    // ---- stage loader: Ahi|Alo|Bhi|Blo, SW64-swizzled 64B rows
    auto load_stage = [&](int kk, int s){
        const uint32_t st = tb + (uint32_t)s * STAGE_BYTES;
        const int k0 = kk * BK;
        #pragma unroll
        for (int i = 0; i < 2; i++){
            int idx = i * 256 + tid;            // 0..511 : 128 rows x 4 16B-chunks
            int r = idx >> 2;
            int c8 = (idx & 3) * 8;             // bf16 col
            uint32_t off = (uint32_t)(r * ROWB + c8 * 2);
            off ^= (off >> 3) & 0x30;           // SW64 swizzle
            size_t ga = (size_t)(m0 + r) * DIM + k0 + c8;
            size_t gb = (size_t)(n0 + r) * DIM + k0 + c8;
            cp16(st + off,                              g_xhi + ga);
            cp16(st + TILE_BYTES + off,                 g_xlo + ga);
            cp16(st + 2*TILE_BYTES + off,               g_whi + gb);
            cp16(st + 3*TILE_BYTES + off,               g_wlo + gb);
        }
        CP_COMMIT();
    };

    float acc[4][4][4];
    #pragma unroll
    for (int a = 0; a < 4; a++)
        #pragma unroll
        for (int b = 0; b < 4; b++)
            #pragma unroll
            for (int c = 0; c < 4; c++) acc[a][b][c] = 0.0f;

    #pragma unroll
    for (int s = 0; s < NSTAGE-1; s++) load_stage(s, s);

    for (int kk = 0; kk < KITER; kk++){
        CP_WAIT(NSTAGE-2);
        __syncthreads();

        if (kk + NSTAGE-1 < KITER) load_stage(kk + NSTAGE-1, (kk + NSTAGE-1) % NSTAGE);
        else CP_COMMIT();   // empty group keeps wait_group accounting exact

        const uint32_t st = tb + (uint32_t)(kk % NSTAGE) * STAGE_BYTES;

        #pragma unroll
        for (int ks = 0; ks < 2; ks++){         // two k16 steps per BK=32
            uint32_t ahi[4][4], alo[4][4], bhi[2][4], blo[2][4];
            #pragma unroll
            for (int mt = 0; mt < 4; mt++){
                int row = wm*64 + mt*16 + (lid & 15);
                uint32_t off = (uint32_t)(row * ROWB + ks*32 + ((lid >> 4) << 4));
                off ^= (off >> 3) & 0x30;
                ldsm4(ahi[mt], st + off);
                ldsm4(alo[mt], st + TILE_BYTES + off);
            }
            #pragma unroll
            for (int nt = 0; nt < 2; nt++){     // each x4 covers 16 n-cols
                int row = wn*32 + nt*16 + (lid & 7) + ((lid >> 4) & 1) * 8;
                uint32_t off = (uint32_t)(row * ROWB + ks*32 + ((lid >> 3) & 1) * 16);
                off ^= (off >> 3) & 0x30;
                ldsm4(bhi[nt], st + 2*TILE_BYTES + off);
                ldsm4(blo[nt], st + 3*TILE_BYTES + off);
            }
            #pragma unroll
            for (int mt = 0; mt < 4; mt++){
                #pragma unroll
                for (int ng = 0; ng < 4; ng++){
                    const uint32_t* bh = &bhi[ng >> 1][(ng & 1) * 2];
                    const uint32_t* bl = &blo[ng >> 1][(ng & 1) * 2];
                    mma16816(acc[mt][ng], ahi[mt], bh);   // hi*hi
                    mma16816(acc[mt][ng], ahi[mt], bl);   // hi*lo
                    mma16816(acc[mt][ng], alo[mt], bh);   // lo*hi
                }
            }
        }
    }

    // ---- epilogue: bias + activation, direct stores (float2, 32B per quad)
    const bool isgate = (n0 < DIM);
    const float* bias = isgate ? bg : bc;
    float* outp = isgate ? g_gate : g_cand;
    const int nb = isgate ? n0 : (n0 - DIM);
    const int g = lid >> 2, t = lid & 3;

    #pragma unroll
    for (int mt = 0; mt < 4; mt++){
        #pragma unroll
        for (int ng = 0; ng < 4; ng++){
            int col = nb + wn*32 + ng*8 + t*2;
            float b0 = bias[col], b1 = bias[col + 1];
            int row0 = m0 + wm*64 + mt*16 + g;
            int row1 = row0 + 8;
            float v00 = acc[mt][ng][0] + b0, v01 = acc[mt][ng][1] + b1;
            float v10 = acc[mt][ng][2] + b0, v11 = acc[mt][ng][3] + b1;
            if (isgate){
                v00 = sigmoid_f(v00); v01 = sigmoid_f(v01);
                v10 = sigmoid_f(v10); v11 = sigmoid_f(v11);
            } else {
                v00 = tanh_f(v00); v01 = tanh_f(v01);
                v10 = tanh_f(v10); v11 = tanh_f(v11);
            }
            *reinterpret_cast<float2*>(outp + (size_t)row0 * DIM + col) = make_float2(v00, v01);
            *reinterpret_cast<float2*>(outp + (size_t)row1 * DIM + col) = make_float2(v10, v11);
        }
    }
}

// ============================================================================
// Kernels 4/5/6: chunked linear-recurrence scan  h_t = g_t*h_{t-1} + c_t
// ============================================================================
__global__ void scan_pass1(){
    int t = blockIdx.x * 256 + threadIdx.x;      // 262144 threads
    int d  = t & (DIM - 1);
    int ch = (t >> 10) & (NCH - 1);
    int b  = t >> 16;
    size_t base = ((size_t)b * SEQ + (size_t)ch * CHUNK_T) * DIM + d;
    float A = 1.0f, H = 0.0f;
    #pragma unroll 4
    for (int i = 0; i < CHUNK_T; i++){
        float g = g_gate[base], c = g_cand[base];
        A *= g;
        H = g * H + c;
        base += DIM;
    }
    size_t sidx = ((size_t)b * NCH + ch) * DIM + d;
    g_Ast[sidx] = A;
    g_Hst[sidx] = H;
}

__global__ void scan_pass2(){
    int t = blockIdx.x * 256 + threadIdx.x;      // 4096 threads
    int d = t & (DIM - 1);
    int b = t >> 10;
    float P = 0.0f;
    #pragma unroll 8
    for (int k = 0; k < NCH; k++){
        size_t s = ((size_t)b * NCH + k) * DIM + d;
        g_Pst[s] = P;
        P = g_Ast[s] * P + g_Hst[s];
    }
}

__global__ void scan_pass3(float* __restrict__ out){
    int t = blockIdx.x * 256 + threadIdx.x;
    int d  = t & (DIM - 1);
    int ch = (t >> 10) & (NCH - 1);
    int b  = t >> 16;
    size_t base = ((size_t)b * SEQ + (size_t)ch * CHUNK_T) * DIM + d;
    size_t sidx = ((size_t)b * NCH + ch) * DIM + d;
    float h = g_Pst[sidx];
    #pragma unroll 4
    for (int i = 0; i < CHUNK_T; i++){
        float g = g_gate[base], c = g_cand[base];
        h = g * h + c;
        out[base] = h;
        base += DIM;
    }
}

// ============================================================================
// Launch
// ============================================================================
extern "C" void kernel_launch(void* const* d_in, const int* in_sizes, int n_in,
                              void* d_out, int out_size){
    (void)in_sizes; (void)n_in; (void)out_size;
    const float* x  = (const float*)d_in[0];
    const float* Wg = (const float*)d_in[1];
    const float* bg = (const float*)d_in[2];
    const float* Wc = (const float*)d_in[3];
    const float* bc = (const float*)d_in[4];
    float* out = (float*)d_out;

    cudaFuncSetAttribute(gemm_kernel, cudaFuncAttributeMaxDynamicSharedMemorySize, GEMM_SMEM);

    conv_x_kernel<<<(MTOT*(size_t)DIM)/4/256, 256>>>(x);              // 32768 blocks
    conv_w_kernel<<<(NTOT*(size_t)DIM)/4/256, 256>>>(Wg, Wc);         // 2048 blocks
    gemm_kernel<<<dim3(NTOT/BN, MTOT/BM), 256, GEMM_SMEM>>>(bg, bc);  // (16, 256)
    scan_pass1<<<(BATCH*NCH*DIM)/256, 256>>>();                       // 1024 blocks
    scan_pass2<<<(BATCH*DIM)/256, 256>>>();                           // 16 blocks
    scan_pass3<<<(BATCH*NCH*DIM)/256, 256>>>(out);                    // 1024 blocks
}

// round 3
// speedup vs baseline: 2.1827x; 2.1827x over previous
#include <cuda_runtime.h>
#include <cuda_fp16.h>
#include <cstdint>
#include <cstddef>

// ============================================================================
// Problem sizes
// ============================================================================
#define BATCH 4
#define SEQ   8192
#define DIM   1024
#define MTOT  (BATCH*SEQ)      // 32768 rows
#define NTOT  (2*DIM)          // 2048 combined output cols (gate | cand)
#define CHUNK_T 128            // scan chunk length
#define NCH   (SEQ/CHUNK_T)    // 64 chunks per (b,d) channel

// ============================================================================
// Scratch (static device arrays — no allocation allowed)
// ============================================================================
__device__ __half g_xh[(size_t)MTOT*DIM];           // 64 MB
__device__ __half g_wh[(size_t)NTOT*DIM];           // 4 MB  (Wg rows 0..1023, Wc rows 1024..2047)
__device__ float g_gate[(size_t)MTOT*DIM];          // 128 MB
__device__ float g_cand[(size_t)MTOT*DIM];          // 128 MB
__device__ float g_Ast[(size_t)BATCH*NCH*DIM];      // 1 MB
__device__ float g_Hst[(size_t)BATCH*NCH*DIM];      // 1 MB
__device__ float g_Pst[(size_t)BATCH*NCH*DIM];      // 1 MB

// ============================================================================
// Helpers (non-'a' PTX only: cp.async, ldmatrix, mma.sync)
// ============================================================================
__device__ __forceinline__ uint32_t smem_u32(const void* p){
    uint32_t a;
    asm("{ .reg .u64 t; cvta.to.shared.u64 t, %1; cvt.u32.u64 %0, t; }" : "=r"(a) : "l"(p));
    return a;
}
__device__ __forceinline__ void cp16(uint32_t smem_addr, const void* gptr){
    asm volatile("cp.async.cg.shared.global [%0], [%1], 16;"
                 :: "r"(smem_addr), "l"(__cvta_generic_to_global(gptr)) : "memory");
}
#define CP_COMMIT()  asm volatile("cp.async.commit_group;" ::: "memory")
#define CP_WAIT(n)   asm volatile("cp.async.wait_group %0;" :: "n"(n) : "memory")

__device__ __forceinline__ void ldsm4(uint32_t* r, uint32_t addr){
    asm volatile("ldmatrix.sync.aligned.m8n8.x4.shared.b16 {%0,%1,%2,%3}, [%4];"
                 : "=r"(r[0]),"=r"(r[1]),"=r"(r[2]),"=r"(r[3]) : "r"(addr));
}
__device__ __forceinline__ void mma16816(float* d, const uint32_t* a, const uint32_t* b){
    asm volatile("mma.sync.aligned.m16n8k16.row.col.f32.f16.f16.f32 "
                 "{%0,%1,%2,%3}, {%4,%5,%6,%7}, {%8,%9}, {%0,%1,%2,%3};"
                 : "+f"(d[0]),"+f"(d[1]),"+f"(d[2]),"+f"(d[3])
                 : "r"(a[0]),"r"(a[1]),"r"(a[2]),"r"(a[3]), "r"(b[0]),"r"(b[1]));
}

__device__ __forceinline__ float sigmoid_f(float v){
    return 1.0f / (1.0f + __expf(-v));
}
__device__ __forceinline__ float tanh_f(float v){
    float a = fabsf(v);
    float e = __expf(-2.0f * a);
    float t = (1.0f - e) / (1.0f + e);
    return copysignf(t, v);
}

// ============================================================================
// Kernel 1: convert x (fp32) -> fp16
// ============================================================================
__global__ void conv_x_kernel(const float* __restrict__ x){
    size_t i = ((size_t)blockIdx.x * blockDim.x + threadIdx.x) * 4;
    float4 v = *reinterpret_cast<const float4*>(x + i);
    __half2* ph = reinterpret_cast<__half2*>(g_xh + i);
    ph[0] = __floats2half2_rn(v.x, v.y);
    ph[1] = __floats2half2_rn(v.z, v.w);
}

// ============================================================================
// Kernel 2: convert [Wg;Wc] (fp32) -> fp16, concatenated rows
// ============================================================================
__global__ void conv_w_kernel(const float* __restrict__ Wg, const float* __restrict__ Wc){
    size_t i = ((size_t)blockIdx.x * blockDim.x + threadIdx.x) * 4;
    const size_t HALF = (size_t)DIM * DIM;
    float4 v = (i < HALF) ? *reinterpret_cast<const float4*>(Wg + i)
                          : *reinterpret_cast<const float4*>(Wc + (i - HALF));
    __half2* ph = reinterpret_cast<__half2*>(g_wh + i);
    ph[0] = __floats2half2_rn(v.x, v.y);
    ph[1] = __floats2half2_rn(v.z, v.w);
}

// ============================================================================
// Kernel 3: fused dual GEMM (mma.sync fp16, fp32 accum)
//   D[m, 0:2048] = x @ [Wg;Wc]^T ; cols < 1024 -> sigmoid -> g_gate
//                                  cols >= 1024 -> tanh   -> g_cand
// ============================================================================
#define BM 128
#define BN 128
#define BK 32
#define NSTAGE 5
#define KITER (DIM/BK)              // 32
#define ROWB 64                     // bytes per smem row (32 halves)
#define TILE_BYTES (128*ROWB)       // 8192 per matrix per stage
#define STAGE_BYTES (2*TILE_BYTES)  // A|B = 16384
#define GEMM_SMEM (NSTAGE*STAGE_BYTES + 128)

__global__ void __launch_bounds__(256, 2)
gemm_kernel(const float* __restrict__ bg, const float* __restrict__ bc){
    extern __shared__ char smem[];
    const uint32_t tb = (smem_u32(smem) + 127u) & ~127u;   // 128B-aligned tile base
    const int tid = threadIdx.x;
    const int wid = tid >> 5;
    const int lid = tid & 31;
    const int wm = wid >> 2;           // 0..1  (64-row slabs)
    const int wn = wid & 3;            // 0..3  (32-col slabs)
    const int n0 = blockIdx.x * BN;
    const int m0 = blockIdx.y * BM;

    // ---- stage loader: A|B, SW64-swizzled 64B rows
    auto load_stage = [&](int kk, int s){
        const uint32_t st = tb + (uint32_t)s * STAGE_BYTES;
        const int k0 = kk * BK;
        #pragma unroll
        for (int i = 0; i < 2; i++){
            int idx = i * 256 + tid;            // 0..511 : 128 rows x 4 16B-chunks
            int r = idx >> 2;
            int c8 = (idx & 3) * 8;             // fp16 col
            uint32_t off = (uint32_t)(r * ROWB + c8 * 2);
            off ^= (off >> 3) & 0x30;           // SW64 swizzle
            size_t ga = (size_t)(m0 + r) * DIM + k0 + c8;
            size_t gb = (size_t)(n0 + r) * DIM + k0 + c8;
            cp16(st + off,              g_xh + ga);
            cp16(st + TILE_BYTES + off, g_wh + gb);
        }
        CP_COMMIT();
    };

    float acc[4][4][4];
    #pragma unroll
    for (int a = 0; a < 4; a++)
        #pragma unroll
        for (int b = 0; b < 4; b++)
            #pragma unroll
            for (int c = 0; c < 4; c++) acc[a][b][c] = 0.0f;

    #pragma unroll
    for (int s = 0; s < NSTAGE-1; s++) load_stage(s, s);

    for (int kk = 0; kk < KITER; kk++){
        CP_WAIT(NSTAGE-2);
        __syncthreads();

        if (kk + NSTAGE-1 < KITER) load_stage(kk + NSTAGE-1, (kk + NSTAGE-1) % NSTAGE);
        else CP_COMMIT();   // empty group keeps wait_group accounting exact

        const uint32_t st = tb + (uint32_t)(kk % NSTAGE) * STAGE_BYTES;

        #pragma unroll
        for (int ks = 0; ks < 2; ks++){         // two k16 steps per BK=32
            uint32_t af[4][4], bf[2][4];
            #pragma unroll
            for (int mt = 0; mt < 4; mt++){
                int row = wm*64 + mt*16 + (lid & 15);
                uint32_t off = (uint32_t)(row * ROWB + ks*32 + ((lid >> 4) << 4));
                off ^= (off >> 3) & 0x30;
                ldsm4(af[mt], st + off);
            }
            #pragma unroll
            for (int nt = 0; nt < 2; nt++){     // each x4 covers 16 n-cols
                int row = wn*32 + nt*16 + (lid & 7) + ((lid >> 4) & 1) * 8;
                uint32_t off = (uint32_t)(row * ROWB + ks*32 + ((lid >> 3) & 1) * 16);
                off ^= (off >> 3) & 0x30;
                ldsm4(bf[nt], st + TILE_BYTES + off);
            }
            #pragma unroll
            for (int mt = 0; mt < 4; mt++){
                #pragma unroll
                for (int ng = 0; ng < 4; ng++){
                    mma16816(acc[mt][ng], af[mt], &bf[ng >> 1][(ng & 1) * 2]);
                }
            }
        }
    }

    // ---- epilogue: bias + activation, direct stores (float2, 32B per quad)
    const bool isgate = (n0 < DIM);
    const float* bias = isgate ? bg : bc;
    float* outp = isgate ? g_gate : g_cand;
    const int nb = isgate ? n0 : (n0 - DIM);
    const int g = lid >> 2, t = lid & 3;

    #pragma unroll
    for (int mt = 0; mt < 4; mt++){
        #pragma unroll
        for (int ng = 0; ng < 4; ng++){
            int col = nb + wn*32 + ng*8 + t*2;
            float b0 = bias[col], b1 = bias[col + 1];
            int row0 = m0 + wm*64 + mt*16 + g;
            int row1 = row0 + 8;
            float v00 = acc[mt][ng][0] + b0, v01 = acc[mt][ng][1] + b1;
            float v10 = acc[mt][ng][2] + b0, v11 = acc[mt][ng][3] + b1;
            if (isgate){
                v00 = sigmoid_f(v00); v01 = sigmoid_f(v01);
                v10 = sigmoid_f(v10); v11 = sigmoid_f(v11);
            } else {
                v00 = tanh_f(v00); v01 = tanh_f(v01);
                v10 = tanh_f(v10); v11 = tanh_f(v11);
            }
            *reinterpret_cast<float2*>(outp + (size_t)row0 * DIM + col) = make_float2(v00, v01);
            *reinterpret_cast<float2*>(outp + (size_t)row1 * DIM + col) = make_float2(v10, v11);
        }
    }
}

// ============================================================================
// Kernels 4/5/6: chunked linear-recurrence scan  h_t = g_t*h_{t-1} + c_t
// Each thread handles 4 adjacent channels (float4).
// ============================================================================
#define D4 (DIM/4)   // 256

__global__ void scan_pass1(){
    int t = blockIdx.x * 256 + threadIdx.x;      // 65536 threads
    int d4 = t & (D4 - 1);
    int ch = (t >> 8) & (NCH - 1);
    int b  = t >> 14;
    const float4* gp = reinterpret_cast<const float4*>(g_gate) +
                       ((size_t)b * SEQ + (size_t)ch * CHUNK_T) * D4 + d4;
    const float4* cp = reinterpret_cast<const float4*>(g_cand) +
                       ((size_t)b * SEQ + (size_t)ch * CHUNK_T) * D4 + d4;
    float4 A = make_float4(1.f,1.f,1.f,1.f);
    float4 H = make_float4(0.f,0.f,0.f,0.f);
    #pragma unroll 4
    for (int i = 0; i < CHUNK_T; i++){
        float4 g = gp[(size_t)i * D4];
        float4 c = cp[(size_t)i * D4];
        A.x *= g.x; A.y *= g.y; A.z *= g.z; A.w *= g.w;
        H.x = g.x*H.x + c.x; H.y = g.y*H.y + c.y;
        H.z = g.z*H.z + c.z; H.w = g.w*H.w + c.w;
    }
    size_t sidx = ((size_t)b * NCH + ch) * D4 + d4;
    reinterpret_cast<float4*>(g_Ast)[sidx] = A;
    reinterpret_cast<float4*>(g_Hst)[sidx] = H;
}

__global__ void scan_pass2(){
    int t = blockIdx.x * 256 + threadIdx.x;      // 1024 threads
    int d4 = t & (D4 - 1);
    int b = t >> 8;
    float4 P = make_float4(0.f,0.f,0.f,0.f);
    for (int k = 0; k < NCH; k++){
        size_t s = ((size_t)b * NCH + k) * D4 + d4;
        reinterpret_cast<float4*>(g_Pst)[s] = P;
        float4 A = reinterpret_cast<const float4*>(g_Ast)[s];
        float4 H = reinterpret_cast<const float4*>(g_Hst)[s];
        P.x = A.x*P.x + H.x; P.y = A.y*P.y + H.y;
        P.z = A.z*P.z + H.z; P.w = A.w*P.w + H.w;
    }
}

__global__ void scan_pass3(float* __restrict__ out){
    int t = blockIdx.x * 256 + threadIdx.x;      // 65536 threads
    int d4 = t & (D4 - 1);
    int ch = (t >> 8) & (NCH - 1);
    int b  = t >> 14;
    size_t base = ((size_t)b * SEQ + (size_t)ch * CHUNK_T) * D4 + d4;
    const float4* gp = reinterpret_cast<const float4*>(g_gate) + base;
    const float4* cp = reinterpret_cast<const float4*>(g_cand) + base;
    float4* op = reinterpret_cast<float4*>(out) + base;
    size_t sidx = ((size_t)b * NCH + ch) * D4 + d4;
    float4 h = reinterpret_cast<const float4*>(g_Pst)[sidx];
    #pragma unroll 4
    for (int i = 0; i < CHUNK_T; i++){
        float4 g = gp[(size_t)i * D4];
        float4 c = cp[(size_t)i * D4];
        h.x = g.x*h.x + c.x; h.y = g.y*h.y + c.y;
        h.z = g.z*h.z + c.z; h.w = g.w*h.w + c.w;
        op[(size_t)i * D4] = h;
    }
}

// ============================================================================
// Launch
// ============================================================================
extern "C" void kernel_launch(void* const* d_in, const int* in_sizes, int n_in,
                              void* d_out, int out_size){
    (void)in_sizes; (void)n_in; (void)out_size;
    const float* x  = (const float*)d_in[0];
    const float* Wg = (const float*)d_in[1];
    const float* bg = (const float*)d_in[2];
    const float* Wc = (const float*)d_in[3];
    const float* bc = (const float*)d_in[4];
    float* out = (float*)d_out;

    cudaFuncSetAttribute(gemm_kernel, cudaFuncAttributeMaxDynamicSharedMemorySize, GEMM_SMEM);

    conv_x_kernel<<<(MTOT*(size_t)DIM)/4/256, 256>>>(x);              // 32768 blocks
    conv_w_kernel<<<(NTOT*(size_t)DIM)/4/256, 256>>>(Wg, Wc);         // 2048 blocks
    gemm_kernel<<<dim3(NTOT/BN, MTOT/BM), 256, GEMM_SMEM>>>(bg, bc);  // (16, 256)
    scan_pass1<<<(BATCH*NCH*D4)/256, 256>>>();                        // 256 blocks
    scan_pass2<<<(BATCH*D4)/256, 256>>>();                            // 4 blocks
    scan_pass3<<<(BATCH*NCH*D4)/256, 256>>>(out);                     // 256 blocks
}

// round 4
// speedup vs baseline: 2.3785x; 1.0897x over previous
#include <cuda_runtime.h>
#include <cuda_fp16.h>
#include <cstdint>
#include <cstddef>

// ============================================================================
// Problem sizes
// ============================================================================
#define BATCH 4
#define SEQ   8192
#define DIM   1024
#define MTOT  (BATCH*SEQ)      // 32768 rows
#define NTOT  (2*DIM)          // 2048 combined output cols (gate | cand)
#define CH_T  64               // scan chunk length
#define NCHK  (SEQ/CH_T)       // 128 chunks per (b,d) channel
#define DV    (DIM/4)          // 256 vec4 channel groups

// ============================================================================
// Scratch (static device arrays — no allocation allowed)
// ============================================================================
__device__ __half g_xh[(size_t)MTOT*DIM];           // 64 MB
__device__ __half g_wh[(size_t)NTOT*DIM];           // 4 MB  (Wg rows 0..1023, Wc rows 1024..2047)
__device__ __half g_gate[(size_t)MTOT*DIM];         // 64 MB
__device__ __half g_cand[(size_t)MTOT*DIM];         // 64 MB
__device__ float g_Ast[(size_t)BATCH*NCHK*DIM];     // 2 MB
__device__ float g_Hst[(size_t)BATCH*NCHK*DIM];     // 2 MB
__device__ float g_Pst[(size_t)BATCH*NCHK*DIM];     // 2 MB

// ============================================================================
// Helpers (non-'a' PTX only: cp.async, ldmatrix, mma.sync)
// ============================================================================
__device__ __forceinline__ uint32_t smem_u32(const void* p){
    uint32_t a;
    asm("{ .reg .u64 t; cvta.to.shared.u64 t, %1; cvt.u32.u64 %0, t; }" : "=r"(a) : "l"(p));
    return a;
}
__device__ __forceinline__ void cp16(uint32_t smem_addr, const void* gptr){
    asm volatile("cp.async.cg.shared.global [%0], [%1], 16;"
                 :: "r"(smem_addr), "l"(__cvta_generic_to_global(gptr)) : "memory");
}
#define CP_COMMIT()  asm volatile("cp.async.commit_group;" ::: "memory")
#define CP_WAIT(n)   asm volatile("cp.async.wait_group %0;" :: "n"(n) : "memory")

__device__ __forceinline__ void ldsm4(uint32_t* r, uint32_t addr){
    asm volatile("ldmatrix.sync.aligned.m8n8.x4.shared.b16 {%0,%1,%2,%3}, [%4];"
                 : "=r"(r[0]),"=r"(r[1]),"=r"(r[2]),"=r"(r[3]) : "r"(addr));
}
__device__ __forceinline__ void mma16816(float* d, const uint32_t* a, const uint32_t* b){
    asm volatile("mma.sync.aligned.m16n8k16.row.col.f32.f16.f16.f32 "
                 "{%0,%1,%2,%3}, {%4,%5,%6,%7}, {%8,%9}, {%0,%1,%2,%3};"
                 : "+f"(d[0]),"+f"(d[1]),"+f"(d[2]),"+f"(d[3])
                 : "r"(a[0]),"r"(a[1]),"r"(a[2]),"r"(a[3]), "r"(b[0]),"r"(b[1]));
}

__device__ __forceinline__ float sigmoid_f(float v){
    return 1.0f / (1.0f + __expf(-v));
}
__device__ __forceinline__ float tanh_f(float v){
    float a = fabsf(v);
    float e = __expf(-2.0f * a);
    float t = (1.0f - e) / (1.0f + e);
    return copysignf(t, v);
}

// ============================================================================
// Kernel 1: convert x (fp32) -> fp16
// ============================================================================
__global__ void conv_x_kernel(const float* __restrict__ x){
    size_t i = ((size_t)blockIdx.x * blockDim.x + threadIdx.x) * 4;
    float4 v = *reinterpret_cast<const float4*>(x + i);
    __half2* ph = reinterpret_cast<__half2*>(g_xh + i);
    ph[0] = __floats2half2_rn(v.x, v.y);
    ph[1] = __floats2half2_rn(v.z, v.w);
}

// ============================================================================
// Kernel 2: convert [Wg;Wc] (fp32) -> fp16, concatenated rows
// ============================================================================
__global__ void conv_w_kernel(const float* __restrict__ Wg, const float* __restrict__ Wc){
    size_t i = ((size_t)blockIdx.x * blockDim.x + threadIdx.x) * 4;
    const size_t HALF = (size_t)DIM * DIM;
    float4 v = (i < HALF) ? *reinterpret_cast<const float4*>(Wg + i)
                          : *reinterpret_cast<const float4*>(Wc + (i - HALF));
    __half2* ph = reinterpret_cast<__half2*>(g_wh + i);
    ph[0] = __floats2half2_rn(v.x, v.y);
    ph[1] = __floats2half2_rn(v.z, v.w);
}

// ============================================================================
// Kernel 3: fused dual GEMM (mma.sync fp16, fp32 accum)
//   D[m, 0:2048] = x @ [Wg;Wc]^T ; cols < 1024 -> sigmoid -> g_gate (fp16)
//                                  cols >= 1024 -> tanh   -> g_cand (fp16)
// ============================================================================
#define BM 128
#define BN 128
#define BK 32
#define NSTAGE 5
#define KITER (DIM/BK)              // 32
#define ROWB 64                     // bytes per smem row (32 halves)
#define TILE_BYTES (128*ROWB)       // 8192 per matrix per stage
#define STAGE_BYTES (2*TILE_BYTES)  // A|B = 16384
#define GEMM_SMEM (NSTAGE*STAGE_BYTES + 128)

__global__ void __launch_bounds__(256, 2)
gemm_kernel(const float* __restrict__ bg, const float* __restrict__ bc){
    extern __shared__ char smem[];
    const uint32_t tb = (smem_u32(smem) + 127u) & ~127u;   // 128B-aligned tile base
    const int tid = threadIdx.x;
    const int wid = tid >> 5;
    const int lid = tid & 31;
    const int wm = wid >> 2;           // 0..1  (64-row slabs)
    const int wn = wid & 3;            // 0..3  (32-col slabs)
    const int n0 = blockIdx.x * BN;
    const int m0 = blockIdx.y * BM;

    // ---- stage loader: A|B, SW64-swizzled 64B rows
    auto load_stage = [&](int kk, int s){
        const uint32_t st = tb + (uint32_t)s * STAGE_BYTES;
        const int k0 = kk * BK;
        #pragma unroll
        for (int i = 0; i < 2; i++){
            int idx = i * 256 + tid;            // 0..511 : 128 rows x 4 16B-chunks
            int r = idx >> 2;
            int c8 = (idx & 3) * 8;             // fp16 col
            uint32_t off = (uint32_t)(r * ROWB + c8 * 2);
            off ^= (off >> 3) & 0x30;           // SW64 swizzle
            size_t ga = (size_t)(m0 + r) * DIM + k0 + c8;
            size_t gb = (size_t)(n0 + r) * DIM + k0 + c8;
            cp16(st + off,              g_xh + ga);
            cp16(st + TILE_BYTES + off, g_wh + gb);
        }
        CP_COMMIT();
    };

    float acc[4][4][4];
    #pragma unroll
    for (int a = 0; a < 4; a++)
        #pragma unroll
        for (int b = 0; b < 4; b++)
            #pragma unroll
            for (int c = 0; c < 4; c++) acc[a][b][c] = 0.0f;

    #pragma unroll
    for (int s = 0; s < NSTAGE-1; s++) load_stage(s, s);

    for (int kk = 0; kk < KITER; kk++){
        CP_WAIT(NSTAGE-2);
        __syncthreads();

        if (kk + NSTAGE-1 < KITER) load_stage(kk + NSTAGE-1, (kk + NSTAGE-1) % NSTAGE);
        else CP_COMMIT();   // empty group keeps wait_group accounting exact

        const uint32_t st = tb + (uint32_t)(kk % NSTAGE) * STAGE_BYTES;

        #pragma unroll
        for (int ks = 0; ks < 2; ks++){         // two k16 steps per BK=32
            uint32_t af[4][4], bf[2][4];
            #pragma unroll
            for (int mt = 0; mt < 4; mt++){
                int row = wm*64 + mt*16 + (lid & 15);
                uint32_t off = (uint32_t)(row * ROWB + ks*32 + ((lid >> 4) << 4));
                off ^= (off >> 3) & 0x30;
                ldsm4(af[mt], st + off);
            }
            #pragma unroll
            for (int nt = 0; nt < 2; nt++){     // each x4 covers 16 n-cols
                int row = wn*32 + nt*16 + (lid & 7) + ((lid >> 4) & 1) * 8;
                uint32_t off = (uint32_t)(row * ROWB + ks*32 + ((lid >> 3) & 1) * 16);
                off ^= (off >> 3) & 0x30;
                ldsm4(bf[nt], st + TILE_BYTES + off);
            }
            #pragma unroll
            for (int mt = 0; mt < 4; mt++){
                #pragma unroll
                for (int ng = 0; ng < 4; ng++){
                    mma16816(acc[mt][ng], af[mt], &bf[ng >> 1][(ng & 1) * 2]);
                }
            }
        }
    }

    // ---- epilogue: bias + activation, fp16 stores (half2)
    const bool isgate = (n0 < DIM);
    const float* bias = isgate ? bg : bc;
    __half* outp = isgate ? g_gate : g_cand;
    const int nb = isgate ? n0 : (n0 - DIM);
    const int g = lid >> 2, t = lid & 3;

    #pragma unroll
    for (int mt = 0; mt < 4; mt++){
        #pragma unroll
        for (int ng = 0; ng < 4; ng++){
            int col = nb + wn*32 + ng*8 + t*2;
            float b0 = bias[col], b1 = bias[col + 1];
            int row0 = m0 + wm*64 + mt*16 + g;
            int row1 = row0 + 8;
            float v00 = acc[mt][ng][0] + b0, v01 = acc[mt][ng][1] + b1;
            float v10 = acc[mt][ng][2] + b0, v11 = acc[mt][ng][3] + b1;
            if (isgate){
                v00 = sigmoid_f(v00); v01 = sigmoid_f(v01);
                v10 = sigmoid_f(v10); v11 = sigmoid_f(v11);
            } else {
                v00 = tanh_f(v00); v01 = tanh_f(v01);
                v10 = tanh_f(v10); v11 = tanh_f(v11);
            }
            *reinterpret_cast<__half2*>(outp + (size_t)row0 * DIM + col) = __floats2half2_rn(v00, v01);
            *reinterpret_cast<__half2*>(outp + (size_t)row1 * DIM + col) = __floats2half2_rn(v10, v11);
        }
    }
}

// ============================================================================
// Kernels 4/5/6: chunked linear-recurrence scan  h_t = g_t*h_{t-1} + c_t
// Each thread handles 4 adjacent channels (8B fp16 loads).
// ============================================================================
__device__ __forceinline__ void load4h(float* f, const __half* p){
    uint2 u = *reinterpret_cast<const uint2*>(p);
    __half2 h0 = *reinterpret_cast<__half2*>(&u.x);
    __half2 h1 = *reinterpret_cast<__half2*>(&u.y);
    float2 a = __half22float2(h0), b = __half22float2(h1);
    f[0] = a.x; f[1] = a.y; f[2] = b.x; f[3] = b.y;
}

__global__ void scan_pass1(){
    int t = blockIdx.x * 256 + threadIdx.x;      // 131072 threads
    int d  = t & (DV - 1);                       // vec4 channel group
    int ch = (t >> 8) & (NCHK - 1);
    int b  = t >> 15;
    size_t base = ((size_t)b * SEQ + (size_t)ch * CH_T) * DIM + (size_t)d * 4;
    float A[4] = {1.f,1.f,1.f,1.f};
    float H[4] = {0.f,0.f,0.f,0.f};
    #pragma unroll 4
    for (int i = 0; i < CH_T; i++){
        float g[4], c[4];
        load4h(g, g_gate + base);
        load4h(c, g_cand + base);
        #pragma unroll
        for (int j = 0; j < 4; j++){
            A[j] *= g[j];
            H[j] = g[j]*H[j] + c[j];
        }
        base += DIM;
    }
    size_t sidx = ((size_t)b * NCHK + ch) * DV + d;
    reinterpret_cast<float4*>(g_Ast)[sidx] = make_float4(A[0],A[1],A[2],A[3]);
    reinterpret_cast<float4*>(g_Hst)[sidx] = make_float4(H[0],H[1],H[2],H[3]);
}

__global__ void scan_pass2(){
    int t = blockIdx.x * 256 + threadIdx.x;      // 1024 threads
    int d = t & (DV - 1);
    int b = t >> 8;
    float4 P = make_float4(0.f,0.f,0.f,0.f);
    #pragma unroll 4
    for (int k = 0; k < NCHK; k++){
        size_t s = ((size_t)b * NCHK + k) * DV + d;
        reinterpret_cast<float4*>(g_Pst)[s] = P;
        float4 A = reinterpret_cast<const float4*>(g_Ast)[s];
        float4 H = reinterpret_cast<const float4*>(g_Hst)[s];
        P.x = A.x*P.x + H.x; P.y = A.y*P.y + H.y;
        P.z = A.z*P.z + H.z; P.w = A.w*P.w + H.w;
    }
}

__global__ void scan_pass3(float* __restrict__ out){
    int t = blockIdx.x * 256 + threadIdx.x;      // 131072 threads
    int d  = t & (DV - 1);
    int ch = (t >> 8) & (NCHK - 1);
    int b  = t >> 15;
    size_t base = ((size_t)b * SEQ + (size_t)ch * CH_T) * DIM + (size_t)d * 4;
    size_t sidx = ((size_t)b * NCHK + ch) * DV + d;
    float4 hp = reinterpret_cast<const float4*>(g_Pst)[sidx];
    float h[4] = {hp.x, hp.y, hp.z, hp.w};
    #pragma unroll 4
    for (int i = 0; i < CH_T; i++){
        float g[4], c[4];
        load4h(g, g_gate + base);
        load4h(c, g_cand + base);
        #pragma unroll
        for (int j = 0; j < 4; j++)
            h[j] = g[j]*h[j] + c[j];
        *reinterpret_cast<float4*>(out + base) = make_float4(h[0],h[1],h[2],h[3]);
        base += DIM;
    }
}

// ============================================================================
// Launch
// ============================================================================
extern "C" void kernel_launch(void* const* d_in, const int* in_sizes, int n_in,
                              void* d_out, int out_size){
    (void)in_sizes; (void)n_in; (void)out_size;
    const float* x  = (const float*)d_in[0];
    const float* Wg = (const float*)d_in[1];
    const float* bg = (const float*)d_in[2];
    const float* Wc = (const float*)d_in[3];
    const float* bc = (const float*)d_in[4];
    float* out = (float*)d_out;

    cudaFuncSetAttribute(gemm_kernel, cudaFuncAttributeMaxDynamicSharedMemorySize, GEMM_SMEM);

    conv_x_kernel<<<(MTOT*(size_t)DIM)/4/256, 256>>>(x);              // 32768 blocks
    conv_w_kernel<<<(NTOT*(size_t)DIM)/4/256, 256>>>(Wg, Wc);         // 2048 blocks
    gemm_kernel<<<dim3(NTOT/BN, MTOT/BM), 256, GEMM_SMEM>>>(bg, bc);  // (16, 256)
    scan_pass1<<<(BATCH*NCHK*DV)/256, 256>>>();                       // 512 blocks
    scan_pass2<<<(BATCH*DV)/256, 256>>>();                            // 4 blocks
    scan_pass3<<<(BATCH*NCHK*DV)/256, 256>>>(out);                    // 512 blocks
}